// round 12
// baseline (speedup 1.0000x reference)
#include <cuda_runtime.h>
#include <cuda_bf16.h>
#include <math.h>

// ---------------------------------------------------------------------------
// Problem constants
// ---------------------------------------------------------------------------
#define BATCH 16
#define NH    128
#define L0    16384
#define KS    4
#define DEPTHS 13
#define LMAX  8192
#define CIN   129

// ---- HMMA config (depths 0..5) ----
#define NT      64
#define NK16    32
#define NMT     24
#define NTH     512
#define NBLK    148
#define BH_WORDS (NK16 * 8 * 32 * 2)   // 16384 u32 per B half

// ---- scalar tail config (depths 6..12) ----
#define TT_OUT 16
#define TTPT   4            // 4 quarters x 4 t's (512 threads)
#define TTIN   (2*TT_OUT + 2)

typedef unsigned long long ull;
typedef unsigned int u32;

// ---------------------------------------------------------------------------
// Device scratch
// ---------------------------------------------------------------------------
__device__ float  g_bufA[(size_t)BATCH * NH * LMAX];
__device__ float  g_bufB[(size_t)BATCH * NH * LMAX];
__device__ float4 g_W4[CIN * 3 * NH];
__device__ u32    g_Wfrag[2 * NK16 * NMT * 32 * 4];
__device__ float  g_Wd[384 * 4];
__device__ float  g_capture[BATCH * NH];
__device__ int    g_Nseq[BATCH][DEPTHS + 1];
__device__ int    g_finish[BATCH];
__device__ int    g_rank[BATCH];
__device__ unsigned g_bar_count = 0;
__device__ unsigned g_bar_gen   = 0;

// ---------------------------------------------------------------------------
// helpers
// ---------------------------------------------------------------------------
__device__ __forceinline__ ull fma2(ull a, ull b, ull c)
{
    ull d;
    asm("fma.rn.f32x2 %0, %1, %2, %3;" : "=l"(d) : "l"(a), "l"(b), "l"(c));
    return d;
}
__device__ __forceinline__ void unpack2f(ull v, float& lo, float& hi)
{
    asm("mov.b64 {%0, %1}, %2;" : "=f"(lo), "=f"(hi) : "l"(v));
}
__device__ __forceinline__ void mma_bf16(float* d, const u32* a, const u32* b)
{
    asm volatile(
        "mma.sync.aligned.m16n8k16.row.col.f32.bf16.bf16.f32 "
        "{%0,%1,%2,%3}, {%4,%5,%6,%7}, {%8,%9}, {%0,%1,%2,%3};"
        : "+f"(d[0]), "+f"(d[1]), "+f"(d[2]), "+f"(d[3])
        : "r"(a[0]), "r"(a[1]), "r"(a[2]), "r"(a[3]), "r"(b[0]), "r"(b[1]));
}
__device__ __forceinline__ u32 pack_bf16x2(float lo16, float hi16)
{
    __nv_bfloat162 t = __floats2bfloat162_rn(lo16, hi16);
    return *reinterpret_cast<u32*>(&t);
}

// Software grid barrier (148 blocks, generation-based). tid-0 arrives/spins.
__device__ __forceinline__ void grid_barrier(int tid)
{
    __syncthreads();
    if (tid == 0) {
        __threadfence();
        unsigned gen = *(volatile unsigned*)&g_bar_gen;
        unsigned old = atomicAdd(&g_bar_count, 1);
        if (old == NBLK - 1) {
            g_bar_count = 0;
            __threadfence();
            atomicAdd(&g_bar_gen, 1);
        } else {
            while (*(volatile unsigned*)&g_bar_gen == gen) { }
        }
        __threadfence();
    }
    __syncthreads();
}

// ---------------------------------------------------------------------------
// ONE persistent kernel: prep -> 6 mma depths -> 7 scalar depths -> finalize
// ---------------------------------------------------------------------------
__global__ __launch_bounds__(NTH, 1)
void fused_kernel(const float* __restrict__ hin,
                  const int* __restrict__ Nin,
                  const float* __restrict__ W,
                  const float* __restrict__ bias,
                  float* __restrict__ out)
{
    const int bid  = blockIdx.x;
    const int tid  = threadIdx.x;
    const int wid  = tid >> 5;
    const int lane = tid & 31;

    extern __shared__ __align__(16) char smem[];
    u32*   Bh   = reinterpret_cast<u32*>(smem);
    u32*   Bl   = Bh + BH_WORDS;
    float* tile = reinterpret_cast<float*>(smem);   // tail union

    // ================= phase 0: prep =================
    if (bid == 0 && tid < BATCH) {
        int b = tid;
        int n = Nin[b];
        g_Nseq[b][0] = n;
        int f = DEPTHS - 1;
        bool done = false;
        #pragma unroll
        for (int d = 0; d < DEPTHS; ++d) {
            int m = n - KS; if (m < 0) m = 0;
            n = (m + 1) / 2 + 1;
            g_Nseq[b][d + 1] = n;
            if (!done && n <= 1) { f = d; done = true; }
        }
        g_finish[b] = f;
    }
    // a-frag weights (hi/lo)
    for (int idx = bid * NTH + tid; idx < 2 * NK16 * NMT * 32 * 4;
         idx += NBLK * NTH) {
        int r     = idx & 3;
        int ln    = (idx >> 2) & 31;
        int mtile = (idx >> 7) % NMT;
        int rest  = (idx >> 7) / NMT;
        int k16   = rest % NK16;
        int hilo  = rest / NK16;
        u32 o = 0;
        #pragma unroll
        for (int i = 0; i < 2; ++i) {
            int m = mtile * 16 + (ln >> 2) + 8 * (r & 1);
            int k = k16 * 16 + (ln & 3) * 2 + 8 * (r >> 1) + i;
            int c = k >> 2, kap = k & 3;
            float w = W[m * (CIN * KS) + c * KS + kap];
            __nv_bfloat16 wh = __float2bfloat16(w);
            float v = hilo ? (w - __bfloat162float(wh)) : w;
            __nv_bfloat16 vb = __float2bfloat16(v);
            o |= ((u32)*reinterpret_cast<unsigned short*>(&vb)) << (16 * i);
        }
        g_Wfrag[idx] = o;
    }
    // tail weights
    for (int i = bid * NTH + tid; i < CIN * 3 * NH; i += NBLK * NTH) {
        int o    = i & 127;
        int gate = (i >> 7) % 3;
        int c    = i / (3 * NH);
        int j    = gate * NH + o;
        g_W4[i] = reinterpret_cast<const float4*>(W)[j * CIN + c];
    }
    // depth-channel weights
    for (int i = bid * NTH + tid; i < 384 * 4; i += NBLK * NTH) {
        int m = i >> 2, k = i & 3;
        g_Wd[i] = W[m * (CIN * KS) + 128 * KS + k];
    }
    grid_barrier(tid);

    // rank (needs all finishes; cheap, every block computes block-locally)
    // (done at finalize by block 0 instead)

    static const int LoutT[DEPTHS] = {8191, 4095, 2047, 1023, 511, 255, 127,
                                      63, 31, 15, 7, 3, 1};
    static const int LinT[DEPTHS]  = {16384, 8191, 4095, 2047, 1023, 511, 255,
                                      127, 63, 31, 15, 7, 3};

    // ================= phases 1..13: depth steps =================
    for (int d = 0; d < DEPTHS; ++d) {
        const float* in = (d == 0) ? hin : ((d & 1) ? g_bufA : g_bufB);
        float* outp = (d & 1) ? g_bufB : g_bufA;
        const int in_stride = (d == 0) ? L0 : LMAX;
        const int Lc   = LinT[d];
        const int Lout = LoutT[d];
        const float logd = log1pf((float)d);

        if (d <= 5) {
            // ---------- HMMA depth ----------
            const int tiles = (Lout + NT - 1) / NT;
            const int jobs  = tiles * BATCH;
            for (int j = bid; j < jobs; j += NBLK) {
                const int b  = j & 15;
                const int t0 = (j >> 4) * NT;
                if (t0 >= g_Nseq[b][d + 1]) continue;

                __syncthreads();   // protect B from previous job's readers

                const int V = min(Lc, g_Nseq[b][d]);
                const float* xb = in + (size_t)b * NH * in_stride;

                // build B fragments (bf16 hi/lo)
                for (int s = tid; s < NK16 * 8 * 32 * 2; s += NTH) {
                    int reg   = s & 1;
                    int ln2   = (s >> 1) & 31;
                    int ntile = (s >> 6) & 7;
                    int k16   = s >> 9;
                    int n  = ntile * 8 + (ln2 >> 2);
                    int kb = k16 * 16 + reg * 8 + (ln2 & 3) * 2;
                    float v0 = 0.f, v1 = 0.f;
                    {
                        int c = kb >> 2, kap = kb & 3;
                        int pos = 2 * (t0 + n) + kap;
                        if (pos < V) v0 = xb[(size_t)c * in_stride + pos];
                    }
                    {
                        int k = kb + 1, c = k >> 2, kap = k & 3;
                        int pos = 2 * (t0 + n) + kap;
                        if (pos < V) v1 = xb[(size_t)c * in_stride + pos];
                    }
                    __nv_bfloat16 h0 = __float2bfloat16(v0);
                    __nv_bfloat16 h1 = __float2bfloat16(v1);
                    u32 H = ((u32)*reinterpret_cast<unsigned short*>(&h0))
                          | (((u32)*reinterpret_cast<unsigned short*>(&h1)) << 16);
                    Bh[s] = H;
                    Bl[s] = pack_bf16x2(v0 - __bfloat162float(h0),
                                        v1 - __bfloat162float(h1));
                }
                __syncthreads();

                const int mw = wid >> 1;
                const int nw = wid & 1;

                float acc[3][4][4];
                #pragma unroll
                for (int g = 0; g < 3; ++g)
                    #pragma unroll
                    for (int ni = 0; ni < 4; ++ni)
                        #pragma unroll
                        for (int r = 0; r < 4; ++r) acc[g][ni][r] = 0.f;

                #pragma unroll 2
                for (int k16 = 0; k16 < NK16; ++k16) {
                    u32 ah[3][4], al[3][4];
                    #pragma unroll
                    for (int g = 0; g < 3; ++g) {
                        int mtile = g * 8 + mw;
                        uint4 vh = *reinterpret_cast<const uint4*>(
                            g_Wfrag + (((0 * NK16 + k16) * NMT + mtile) * 32 + lane) * 4);
                        uint4 vl = *reinterpret_cast<const uint4*>(
                            g_Wfrag + (((1 * NK16 + k16) * NMT + mtile) * 32 + lane) * 4);
                        ah[g][0] = vh.x; ah[g][1] = vh.y; ah[g][2] = vh.z; ah[g][3] = vh.w;
                        al[g][0] = vl.x; al[g][1] = vl.y; al[g][2] = vl.z; al[g][3] = vl.w;
                    }
                    u32 bh[4][2], bl[4][2];
                    #pragma unroll
                    for (int ni = 0; ni < 4; ++ni) {
                        int ntile = nw * 4 + ni;
                        uint2 vb = *reinterpret_cast<const uint2*>(
                            Bh + ((k16 * 8 + ntile) * 32 + lane) * 2);
                        uint2 wb = *reinterpret_cast<const uint2*>(
                            Bl + ((k16 * 8 + ntile) * 32 + lane) * 2);
                        bh[ni][0] = vb.x; bh[ni][1] = vb.y;
                        bl[ni][0] = wb.x; bl[ni][1] = wb.y;
                    }
                    #pragma unroll
                    for (int g = 0; g < 3; ++g)
                        #pragma unroll
                        for (int ni = 0; ni < 4; ++ni) {
                            mma_bf16(acc[g][ni], ah[g], bh[ni]);
                            mma_bf16(acc[g][ni], ah[g], bl[ni]);
                            mma_bf16(acc[g][ni], al[g], bh[ni]);
                        }
                }

                // epilogue
                const int rowa = 16 * mw + (lane >> 2);
                const int rowb = rowa + 8;
                const float biasv[2][3] = {
                    { bias[rowa], bias[NH + rowa], bias[2 * NH + rowa] },
                    { bias[rowb], bias[NH + rowb], bias[2 * NH + rowb] } };
                float4 wd[2][3];
                float fsum[2][3];
                #pragma unroll
                for (int rs = 0; rs < 2; ++rs)
                    #pragma unroll
                    for (int g = 0; g < 3; ++g) {
                        int row = rs ? rowb : rowa;
                        wd[rs][g] = *reinterpret_cast<const float4*>(
                            g_Wd + (g * 128 + row) * 4);
                        fsum[rs][g] = logd * (wd[rs][g].x + wd[rs][g].y
                                            + wd[rs][g].z + wd[rs][g].w);
                    }
                const int fin_here = (g_finish[b] == d);
                #pragma unroll
                for (int ni = 0; ni < 4; ++ni) {
                    int col0 = t0 + 32 * nw + ni * 8 + (lane & 3) * 2;
                    #pragma unroll
                    for (int rs = 0; rs < 2; ++rs) {
                        int row = rs ? rowb : rowa;
                        float* orow = outp + ((size_t)b * NH + row) * LMAX;
                        #pragma unroll
                        for (int cc = 0; cc < 2; ++cc) {
                            int col = col0 + cc;
                            if (col < Lout) {
                                int ci = rs * 2 + cc;
                                float dt[3];
                                int p2 = 2 * col;
                                if (p2 + 3 < V) {
                                    dt[0] = fsum[rs][0]; dt[1] = fsum[rs][1];
                                    dt[2] = fsum[rs][2];
                                } else {
                                    float m0 = (p2 < V) ? logd : 0.f;
                                    float m1 = (p2+1 < V) ? logd : 0.f;
                                    float m2 = (p2+2 < V) ? logd : 0.f;
                                    float m3 = (p2+3 < V) ? logd : 0.f;
                                    #pragma unroll
                                    for (int g = 0; g < 3; ++g)
                                        dt[g] = wd[rs][g].x*m0 + wd[rs][g].y*m1
                                              + wd[rs][g].z*m2 + wd[rs][g].w*m3;
                                }
                                float l  = acc[0][ni][ci] + biasv[rs][0] + dt[0];
                                float rr = acc[1][ni][ci] + biasv[rs][1] + dt[1];
                                float ga = acc[2][ni][ci] + biasv[rs][2] + dt[2];
                                float gv = 1.0f / (1.0f + __expf(-ga));
                                float rv = tanhf(rr);
                                float hn = l * gv + rv * (1.0f - gv);
                                orow[col] = hn;
                                if (col == 0 && fin_here)
                                    g_capture[b * NH + row] = hn;
                            }
                        }
                    }
                }
            }
        } else {
            // ---------- scalar tail depth ----------
            const int tiles = (Lout + TT_OUT - 1) / TT_OUT;
            const int jobs  = tiles * BATCH;
            for (int j = bid; j < jobs; j += NBLK) {
                const int b  = j & 15;
                const int t0 = (j >> 4) * TT_OUT;
                if (t0 >= g_Nseq[b][d + 1]) continue;

                __syncthreads();
                const int V = min(Lc, g_Nseq[b][d]);
                const float* inb = in + (size_t)b * NH * LMAX;
                for (int i = tid; i < CIN * TTIN; i += NTH) {
                    int c = i / TTIN;
                    int x = i - c * TTIN;
                    int pos = 2 * t0 + x;
                    float v = 0.0f;
                    if (pos < V) v = (c < NH) ? inb[(size_t)c * LMAX + pos] : logd;
                    tile[i] = v;
                }
                __syncthreads();

                const int o   = tid & 127;
                const int qt  = tid >> 7;          // 0..3
                const int tl0 = qt * TTPT;

                ull accl[TTPT], accr[TTPT], accg[TTPT];
                #pragma unroll
                for (int tt = 0; tt < TTPT; ++tt) {
                    accl[tt] = 0ull; accr[tt] = 0ull; accg[tt] = 0ull;
                }
                const ulonglong2* wbase =
                    reinterpret_cast<const ulonglong2*>(g_W4);
                #pragma unroll 1
                for (int c = 0; c < CIN; ++c) {
                    const ulonglong2 wl = wbase[(c * 3 + 0) * NH + o];
                    const ulonglong2 wr = wbase[(c * 3 + 1) * NH + o];
                    const ulonglong2 wg = wbase[(c * 3 + 2) * NH + o];
                    const ull* xr = reinterpret_cast<const ull*>(
                        tile + c * TTIN + 2 * tl0);
                    ull x0 = xr[0];
                    #pragma unroll
                    for (int tt = 0; tt < TTPT; ++tt) {
                        ull x1 = xr[tt + 1];
                        accl[tt] = fma2(wl.x, x0, accl[tt]);
                        accl[tt] = fma2(wl.y, x1, accl[tt]);
                        accr[tt] = fma2(wr.x, x0, accr[tt]);
                        accr[tt] = fma2(wr.y, x1, accr[tt]);
                        accg[tt] = fma2(wg.x, x0, accg[tt]);
                        accg[tt] = fma2(wg.y, x1, accg[tt]);
                        x0 = x1;
                    }
                }
                const float bl2 = bias[o], br2 = bias[NH + o], bg2 = bias[2*NH + o];
                const int fin_here = (g_finish[b] == d);
                float* outb = outp + ((size_t)b * NH + o) * LMAX;
                #pragma unroll
                for (int tt = 0; tt < TTPT; ++tt) {
                    int t = t0 + tl0 + tt;
                    if (t < Lout) {
                        float lo, hi;
                        unpack2f(accl[tt], lo, hi); float l  = lo + hi + bl2;
                        unpack2f(accr[tt], lo, hi); float rr = lo + hi + br2;
                        unpack2f(accg[tt], lo, hi); float ga = lo + hi + bg2;
                        float gv = 1.0f / (1.0f + __expf(-ga));
                        float rv = tanhf(rr);
                        float hn = l * gv + rv * (1.0f - gv);
                        outb[t] = hn;
                        if (t == 0 && fin_here) g_capture[b * NH + o] = hn;
                    }
                }
            }
        }
        grid_barrier(tid);
    }

    // ================= finalize =================
    if (bid == 0) {
        __shared__ int rank_s[BATCH];
        if (tid < BATCH) {
            int f = g_finish[tid], r = 0;
            #pragma unroll
            for (int j = 0; j < BATCH; ++j) {
                int fj = g_finish[j];
                if (fj < f || (fj == f && j < tid)) r++;
            }
            rank_s[tid] = r;
        }
        __syncthreads();
        for (int i = tid; i < BATCH * NH; i += NTH) {
            int s = i >> 7, o = i & 127;
            out[rank_s[s] * NH + o] = g_capture[i];
        }
    }
}

// ---------------------------------------------------------------------------
// Launch: ONE kernel
// ---------------------------------------------------------------------------
extern "C" void kernel_launch(void* const* d_in, const int* in_sizes, int n_in,
                              void* d_out, int out_size)
{
    const float* h    = (const float*)d_in[0];
    const int*   N    = (const int*)  d_in[1];
    const float* W    = (const float*)d_in[2];
    const float* bias = (const float*)d_in[3];
    float* out = (float*)d_out;

    const int SMEM_DYN = 2 * BH_WORDS * (int)sizeof(u32);   // 131072 B
    cudaFuncSetAttribute(fused_kernel,
                         cudaFuncAttributeMaxDynamicSharedMemorySize, SMEM_DYN);

    fused_kernel<<<NBLK, NTH, SMEM_DYN>>>(h, N, W, bias, out);
}

// round 13
// speedup vs baseline: 1.7230x; 1.7230x over previous
#include <cuda_runtime.h>
#include <cuda_bf16.h>
#include <math.h>

// ---------------------------------------------------------------------------
// Problem constants
// ---------------------------------------------------------------------------
#define BATCH 16
#define NH    128
#define L0    16384
#define KS    4
#define DEPTHS 13
#define LMAX  8192
#define CIN   129

// ---- HMMA kernel config (depths 0..5) ----
#define NT      64          // t's per block (8 n-tiles of 8)
#define NK16    32          // k16 fragments (K = 512)
#define NMT     24          // m-tiles (384 rows / 16)
#define MMA_NTH 512         // 16 warps
#define BH_WORDS (NK16 * 8 * 32 * 2)     // 16384 u32 per B half

// ---- fused tail config (depths 6..12) ----
#define TT_OUT 16
#define TTPT   8
#define TTIN   (2*TT_OUT + 2)
#define TAIL_NBLK 128
#define TAIL_NTH  256

typedef unsigned long long ull;
typedef unsigned int u32;

// ---------------------------------------------------------------------------
// Device scratch
// ---------------------------------------------------------------------------
__device__ float  g_bufA[(size_t)BATCH * NH * LMAX];
__device__ float  g_bufB[(size_t)BATCH * NH * LMAX];
__device__ float4 g_W4[CIN * 3 * NH];                  // tail weights
__device__ u32    g_Wfrag[2 * NK16 * NMT * 32 * 4];    // a-frag-ordered bf16 hi/lo
__device__ float  g_Wd[384 * 4];                       // depth-channel weights
__device__ float  g_capture[BATCH * NH];
__device__ int    g_Nseq[BATCH][DEPTHS + 1];
__device__ int    g_finish[BATCH];
__device__ unsigned g_bar_count = 0;
__device__ unsigned g_bar_gen   = 0;

// ---------------------------------------------------------------------------
// helpers
// ---------------------------------------------------------------------------
__device__ __forceinline__ ull fma2(ull a, ull b, ull c)
{
    ull d;
    asm("fma.rn.f32x2 %0, %1, %2, %3;" : "=l"(d) : "l"(a), "l"(b), "l"(c));
    return d;
}
__device__ __forceinline__ void unpack2f(ull v, float& lo, float& hi)
{
    asm("mov.b64 {%0, %1}, %2;" : "=f"(lo), "=f"(hi) : "l"(v));
}
__device__ __forceinline__ void mma_bf16(float* d, const u32* a, const u32* b)
{
    asm volatile(
        "mma.sync.aligned.m16n8k16.row.col.f32.bf16.bf16.f32 "
        "{%0,%1,%2,%3}, {%4,%5,%6,%7}, {%8,%9}, {%0,%1,%2,%3};"
        : "+f"(d[0]), "+f"(d[1]), "+f"(d[2]), "+f"(d[3])
        : "r"(a[0]), "r"(a[1]), "r"(a[2]), "r"(a[3]), "r"(b[0]), "r"(b[1]));
}
__device__ __forceinline__ u32 pack_bf16x2(float lo16, float hi16)
{
    __nv_bfloat162 t = __floats2bfloat162_rn(lo16, hi16);
    return *reinterpret_cast<u32*>(&t);
}

// ---------------------------------------------------------------------------
// Prep: N recurrence, finish depth
// ---------------------------------------------------------------------------
__global__ void prep_meta_kernel(const int* __restrict__ N)
{
    int b = threadIdx.x;
    if (b < BATCH) {
        int n = N[b];
        g_Nseq[b][0] = n;
        int f = DEPTHS - 1;
        bool done = false;
        #pragma unroll
        for (int d = 0; d < DEPTHS; ++d) {
            int m = n - KS; if (m < 0) m = 0;
            n = (m + 1) / 2 + 1;
            g_Nseq[b][d + 1] = n;
            if (!done && n <= 1) { f = d; done = true; }
        }
        g_finish[b] = f;
    }
}

// ---------------------------------------------------------------------------
// Prep: tail weights (g_W4)
// ---------------------------------------------------------------------------
__global__ void prep_wt_kernel(const float* __restrict__ W)
{
    int i = blockIdx.x * blockDim.x + threadIdx.x;
    if (i < CIN * 3 * NH) {
        int o    = i & 127;
        int gate = (i >> 7) % 3;
        int c    = i / (3 * NH);
        int j    = gate * NH + o;
        const float4* src = reinterpret_cast<const float4*>(W);
        g_W4[i] = src[j * CIN + c];
    }
}

// ---------------------------------------------------------------------------
// Prep: a-fragment-ordered bf16 hi/lo weights + depth-channel weights
// ---------------------------------------------------------------------------
__global__ void prep_wfrag_kernel(const float* __restrict__ W)
{
    int idx = blockIdx.x * blockDim.x + threadIdx.x;
    const int TOT = 2 * NK16 * NMT * 32 * 4;
    if (idx < TOT) {
        int r     = idx & 3;
        int lane  = (idx >> 2) & 31;
        int mtile = (idx >> 7) % NMT;
        int rest  = (idx >> 7) / NMT;
        int k16   = rest % NK16;
        int hilo  = rest / NK16;
        u32 out = 0;
        #pragma unroll
        for (int i = 0; i < 2; ++i) {
            int m = mtile * 16 + (lane >> 2) + 8 * (r & 1);
            int k = k16 * 16 + (lane & 3) * 2 + 8 * (r >> 1) + i;
            int c = k >> 2, kap = k & 3;
            float w = W[m * (CIN * KS) + c * KS + kap];
            __nv_bfloat16 wh = __float2bfloat16(w);
            float v = hilo ? (w - __bfloat162float(wh)) : w;
            __nv_bfloat16 vb = __float2bfloat16(v);
            out |= ((u32)*reinterpret_cast<unsigned short*>(&vb)) << (16 * i);
        }
        g_Wfrag[idx] = out;
    }
    if (idx < 384 * 4) {
        int m = idx >> 2, k = idx & 3;
        g_Wd[idx] = W[m * (CIN * KS) + 128 * KS + k];
    }
}

// ---------------------------------------------------------------------------
// HMMA depth step (d = 0..5): R9-proven. One block = 64 t's of one batch.
// ---------------------------------------------------------------------------
__global__ __launch_bounds__(MMA_NTH, 1)
void conv_mma_kernel(const float* __restrict__ hin,
                     int insel, int outsel, int in_stride,
                     int Lc, int Lout, int depth, float logd,
                     const float* __restrict__ bias)
{
    const int b  = blockIdx.y;
    const int t0 = blockIdx.x * NT;
    if (t0 >= g_Nseq[b][depth + 1]) return;

    const float* in = (insel == 0) ? hin : (insel == 1 ? g_bufA : g_bufB);
    float* out = (outsel == 1) ? g_bufA : g_bufB;

    extern __shared__ __align__(16) char smem[];
    u32* Bh = reinterpret_cast<u32*>(smem);
    u32* Bl = Bh + BH_WORDS;

    const int tid = threadIdx.x;
    const int V = min(Lc, g_Nseq[b][depth]);
    const float* xb = in + (size_t)b * NH * in_stride;

    // ---- build B (x) fragments, bf16 hi/lo ----
    for (int s = tid; s < NK16 * 8 * 32 * 2; s += MMA_NTH) {
        int reg   = s & 1;
        int lane2 = (s >> 1) & 31;
        int ntile = (s >> 6) & 7;
        int k16   = s >> 9;
        int n  = ntile * 8 + (lane2 >> 2);
        int kb = k16 * 16 + reg * 8 + (lane2 & 3) * 2;
        float v0 = 0.f, v1 = 0.f;
        {
            int c = kb >> 2, kap = kb & 3;
            int pos = 2 * (t0 + n) + kap;
            if (pos < V) v0 = xb[(size_t)c * in_stride + pos];
        }
        {
            int k = kb + 1, c = k >> 2, kap = k & 3;
            int pos = 2 * (t0 + n) + kap;
            if (pos < V) v1 = xb[(size_t)c * in_stride + pos];
        }
        __nv_bfloat16 h0 = __float2bfloat16(v0);
        __nv_bfloat16 h1 = __float2bfloat16(v1);
        u32 H = ((u32)*reinterpret_cast<unsigned short*>(&h0))
              | (((u32)*reinterpret_cast<unsigned short*>(&h1)) << 16);
        Bh[s] = H;
        Bl[s] = pack_bf16x2(v0 - __bfloat162float(h0),
                            v1 - __bfloat162float(h1));
    }
    __syncthreads();

    const int wid  = tid >> 5;
    const int lane = tid & 31;
    const int mw   = wid >> 1;
    const int nw   = wid & 1;

    float acc[3][4][4];
    #pragma unroll
    for (int g = 0; g < 3; ++g)
        #pragma unroll
        for (int ni = 0; ni < 4; ++ni)
            #pragma unroll
            for (int r = 0; r < 4; ++r) acc[g][ni][r] = 0.f;

    #pragma unroll 2
    for (int k16 = 0; k16 < NK16; ++k16) {
        u32 ah[3][4], al[3][4];
        #pragma unroll
        for (int g = 0; g < 3; ++g) {
            int mtile = g * 8 + mw;
            uint4 vh = *reinterpret_cast<const uint4*>(
                g_Wfrag + (((0 * NK16 + k16) * NMT + mtile) * 32 + lane) * 4);
            uint4 vl = *reinterpret_cast<const uint4*>(
                g_Wfrag + (((1 * NK16 + k16) * NMT + mtile) * 32 + lane) * 4);
            ah[g][0] = vh.x; ah[g][1] = vh.y; ah[g][2] = vh.z; ah[g][3] = vh.w;
            al[g][0] = vl.x; al[g][1] = vl.y; al[g][2] = vl.z; al[g][3] = vl.w;
        }
        u32 bh[4][2], bl[4][2];
        #pragma unroll
        for (int ni = 0; ni < 4; ++ni) {
            int ntile = nw * 4 + ni;
            uint2 vb = *reinterpret_cast<const uint2*>(
                Bh + ((k16 * 8 + ntile) * 32 + lane) * 2);
            uint2 wb = *reinterpret_cast<const uint2*>(
                Bl + ((k16 * 8 + ntile) * 32 + lane) * 2);
            bh[ni][0] = vb.x; bh[ni][1] = vb.y;
            bl[ni][0] = wb.x; bl[ni][1] = wb.y;
        }
        #pragma unroll
        for (int g = 0; g < 3; ++g)
            #pragma unroll
            for (int ni = 0; ni < 4; ++ni) {
                mma_bf16(acc[g][ni], ah[g], bh[ni]);
                mma_bf16(acc[g][ni], ah[g], bl[ni]);
                mma_bf16(acc[g][ni], al[g], bh[ni]);
            }
    }

    // ---- epilogue ----
    const int rowa = 16 * mw + (lane >> 2);
    const int rowb = rowa + 8;
    const float biasv[2][3] = {
        { bias[rowa], bias[NH + rowa], bias[2 * NH + rowa] },
        { bias[rowb], bias[NH + rowb], bias[2 * NH + rowb] } };
    float4 wd[2][3];
    float fsum[2][3];
    #pragma unroll
    for (int rs = 0; rs < 2; ++rs)
        #pragma unroll
        for (int g = 0; g < 3; ++g) {
            int row = rs ? rowb : rowa;
            wd[rs][g] = *reinterpret_cast<const float4*>(g_Wd + (g * 128 + row) * 4);
            fsum[rs][g] = logd * (wd[rs][g].x + wd[rs][g].y + wd[rs][g].z + wd[rs][g].w);
        }

    const int fin_here = (g_finish[b] == depth);
    #pragma unroll
    for (int ni = 0; ni < 4; ++ni) {
        int col0 = t0 + 32 * nw + ni * 8 + (lane & 3) * 2;
        #pragma unroll
        for (int rs = 0; rs < 2; ++rs) {
            int row = rs ? rowb : rowa;
            float* orow = out + ((size_t)b * NH + row) * LMAX;
            #pragma unroll
            for (int cc = 0; cc < 2; ++cc) {
                int col = col0 + cc;
                if (col < Lout) {
                    int ci = rs * 2 + cc;
                    float dt[3];
                    int p2 = 2 * col;
                    if (p2 + 3 < V) {
                        dt[0] = fsum[rs][0]; dt[1] = fsum[rs][1]; dt[2] = fsum[rs][2];
                    } else {
                        float m0 = (p2 < V) ? logd : 0.f, m1 = (p2+1 < V) ? logd : 0.f;
                        float m2 = (p2+2 < V) ? logd : 0.f, m3 = (p2+3 < V) ? logd : 0.f;
                        #pragma unroll
                        for (int g = 0; g < 3; ++g)
                            dt[g] = wd[rs][g].x*m0 + wd[rs][g].y*m1
                                  + wd[rs][g].z*m2 + wd[rs][g].w*m3;
                    }
                    float l  = acc[0][ni][ci] + biasv[rs][0] + dt[0];
                    float rr = acc[1][ni][ci] + biasv[rs][1] + dt[1];
                    float ga = acc[2][ni][ci] + biasv[rs][2] + dt[2];
                    float gv = 1.0f / (1.0f + __expf(-ga));
                    float rv = tanhf(rr);
                    float hn = l * gv + rv * (1.0f - gv);
                    orow[col] = hn;
                    if (col == 0 && fin_here) g_capture[b * NH + row] = hn;
                }
            }
        }
    }
}

// ---------------------------------------------------------------------------
// Fused tail (d = 6..12) + finalize: ONE persistent launch, 128 co-resident
// blocks, software grid barrier between depths. Job body = proven R2 tail.
// ---------------------------------------------------------------------------
__device__ __forceinline__ void tail_grid_barrier(int tid)
{
    __syncthreads();
    if (tid == 0) {
        __threadfence();
        unsigned gen = *(volatile unsigned*)&g_bar_gen;
        unsigned old = atomicAdd(&g_bar_count, 1);
        if (old == TAIL_NBLK - 1) {
            g_bar_count = 0;
            __threadfence();
            atomicAdd(&g_bar_gen, 1);
        } else {
            while (*(volatile unsigned*)&g_bar_gen == gen) { }
        }
        __threadfence();
    }
    __syncthreads();
}

__global__ __launch_bounds__(TAIL_NTH)
void tail_fused_kernel(const float* __restrict__ bias, float* __restrict__ out)
{
    const int bid = blockIdx.x;
    const int tid = threadIdx.x;

    __shared__ float tile[CIN][TTIN];

    static const int LoutT[7] = {127, 63, 31, 15, 7, 3, 1};
    static const int LinT[7]  = {255, 127, 63, 31, 15, 7, 3};

    #pragma unroll 1
    for (int di = 0; di < 7; ++di) {
        const int d    = 6 + di;
        const int Lc   = LinT[di];
        const int Lout = LoutT[di];
        const float logd = log1pf((float)d);
        const float* in = (d & 1) ? g_bufA : g_bufB;
        float* outp = (d & 1) ? g_bufB : g_bufA;

        const int tiles = (Lout + TT_OUT - 1) / TT_OUT;
        const int jobs  = tiles * BATCH;
        for (int j = bid; j < jobs; j += TAIL_NBLK) {
            const int b  = j & 15;
            const int t0 = (j >> 4) * TT_OUT;
            if (t0 >= g_Nseq[b][d + 1]) continue;

            __syncthreads();   // prior job's tile readers done
            const int V = min(Lc, g_Nseq[b][d]);
            const float* inb = in + (size_t)b * NH * LMAX;
            for (int i = tid; i < CIN * TTIN; i += TAIL_NTH) {
                int c = i / TTIN;
                int x = i - c * TTIN;
                int pos = 2 * t0 + x;
                float v = 0.0f;
                if (pos < V) v = (c < NH) ? inb[(size_t)c * LMAX + pos] : logd;
                tile[c][x] = v;
            }
            __syncthreads();

            const int o    = tid & 127;
            const int half = tid >> 7;
            const int tl0  = half * TTPT;

            ull accl[TTPT], accr[TTPT], accg[TTPT];
            #pragma unroll
            for (int tt = 0; tt < TTPT; ++tt) {
                accl[tt] = 0ull; accr[tt] = 0ull; accg[tt] = 0ull;
            }
            const ulonglong2* wbase = reinterpret_cast<const ulonglong2*>(g_W4);
            #pragma unroll 1
            for (int c = 0; c < CIN; ++c) {
                const ulonglong2 wl = wbase[(c * 3 + 0) * NH + o];
                const ulonglong2 wr = wbase[(c * 3 + 1) * NH + o];
                const ulonglong2 wg = wbase[(c * 3 + 2) * NH + o];
                const ull* xr = reinterpret_cast<const ull*>(&tile[c][2 * tl0]);
                ull x0 = xr[0];
                #pragma unroll
                for (int tt = 0; tt < TTPT; ++tt) {
                    ull x1 = xr[tt + 1];
                    accl[tt] = fma2(wl.x, x0, accl[tt]);
                    accl[tt] = fma2(wl.y, x1, accl[tt]);
                    accr[tt] = fma2(wr.x, x0, accr[tt]);
                    accr[tt] = fma2(wr.y, x1, accr[tt]);
                    accg[tt] = fma2(wg.x, x0, accg[tt]);
                    accg[tt] = fma2(wg.y, x1, accg[tt]);
                    x0 = x1;
                }
            }
            const float bl = bias[o], br = bias[NH + o], bg = bias[2 * NH + o];
            const int fin_here = (g_finish[b] == d);
            float* outb = outp + ((size_t)b * NH + o) * LMAX;
            #pragma unroll
            for (int tt = 0; tt < TTPT; ++tt) {
                int t = t0 + tl0 + tt;
                if (t < Lout) {
                    float lo, hi;
                    unpack2f(accl[tt], lo, hi); float l  = lo + hi + bl;
                    unpack2f(accr[tt], lo, hi); float rr = lo + hi + br;
                    unpack2f(accg[tt], lo, hi); float ga = lo + hi + bg;
                    float gv = 1.0f / (1.0f + __expf(-ga));
                    float rv = tanhf(rr);
                    float hn = l * gv + rv * (1.0f - gv);
                    outb[t] = hn;
                    if (t == 0 && fin_here) g_capture[b * NH + o] = hn;
                }
            }
        }
        tail_grid_barrier(tid);
    }

    // finalize (rank + reorder) by block 0
    if (bid == 0) {
        __shared__ int rank_s[BATCH];
        if (tid < BATCH) {
            int f = g_finish[tid], r = 0;
            #pragma unroll
            for (int j = 0; j < BATCH; ++j) {
                int fj = g_finish[j];
                if (fj < f || (fj == f && j < tid)) r++;
            }
            rank_s[tid] = r;
        }
        __syncthreads();
        for (int i = tid; i < BATCH * NH; i += TAIL_NTH) {
            int s = i >> 7, o = i & 127;
            out[rank_s[s] * NH + o] = g_capture[i];
        }
    }
}

// ---------------------------------------------------------------------------
// Launch: 3 prep + 6 mma + 1 fused tail
// ---------------------------------------------------------------------------
extern "C" void kernel_launch(void* const* d_in, const int* in_sizes, int n_in,
                              void* d_out, int out_size)
{
    const float* h    = (const float*)d_in[0];
    const int*   N    = (const int*)  d_in[1];
    const float* W    = (const float*)d_in[2];
    const float* bias = (const float*)d_in[3];
    float* out = (float*)d_out;

    const int SMEM_DYN = 2 * BH_WORDS * (int)sizeof(u32);   // 131072 B
    cudaFuncSetAttribute(conv_mma_kernel,
                         cudaFuncAttributeMaxDynamicSharedMemorySize, SMEM_DYN);

    prep_meta_kernel<<<1, 32>>>(N);
    prep_wt_kernel<<<(CIN * 3 * NH + 255) / 256, 256>>>(W);
    prep_wfrag_kernel<<<(2 * NK16 * NMT * 32 * 4 + 255) / 256, 256>>>(W);

    static const int Lin[6]   = {16384, 8191, 4095, 2047, 1023, 511};
    static const int LoutA[6] = {8191, 4095, 2047, 1023, 511, 255};

    for (int d = 0; d < 6; ++d) {
        int insel  = (d == 0) ? 0 : ((d & 1) ? 1 : 2);
        int outsel = (d & 1) ? 2 : 1;
        int in_stride = (d == 0) ? L0 : LMAX;
        float logd = log1pf((float)d);
        dim3 grid((LoutA[d] + NT - 1) / NT, BATCH);
        conv_mma_kernel<<<grid, MMA_NTH, SMEM_DYN>>>(
            h, insel, outsel, in_stride, Lin[d], LoutA[d], d, logd, bias);
    }

    tail_fused_kernel<<<TAIL_NBLK, TAIL_NTH>>>(bias, out);
}

// round 14
// speedup vs baseline: 2.1969x; 1.2750x over previous
#include <cuda_runtime.h>
#include <cuda_fp16.h>
#include <math.h>

// ---------------------------------------------------------------------------
// Problem constants
// ---------------------------------------------------------------------------
#define BATCH 16
#define NH    128
#define L0    16384
#define KS    4
#define DEPTHS 13
#define LMAX  8192
#define CIN   129

// ---- HMMA kernel config (depths 0..5) ----
#define NT      64          // t's per block (8 n-tiles of 8)
#define NK16    32          // k16 fragments (K = 512)
#define NMT     24          // m-tiles (384 rows / 16)
#define MMA_NTH 512         // 16 warps
#define BH_WORDS (NK16 * 8 * 32 * 2)     // 16384 u32 per B half

// ---- scalar tail config (depths 6..12) ----
#define TT_OUT 16
#define TTPT   8
#define TTIN   (2*TT_OUT + 2)

typedef unsigned long long ull;
typedef unsigned int u32;

// ---------------------------------------------------------------------------
// Device scratch
// ---------------------------------------------------------------------------
__device__ float  g_bufA[(size_t)BATCH * NH * LMAX];
__device__ float  g_bufB[(size_t)BATCH * NH * LMAX];
__device__ float4 g_W4[CIN * 3 * NH];               // tail weights (fp32)
__device__ u32    g_Wfrag[NK16 * NMT * 32 * 4];     // a-frag-ordered fp16 W
__device__ float  g_Wd[384 * 4];                    // depth-channel weights
__device__ float  g_capture[BATCH * NH];
__device__ int    g_Nseq[BATCH][DEPTHS + 1];
__device__ int    g_finish[BATCH];
__device__ int    g_rank[BATCH];

// ---------------------------------------------------------------------------
// helpers
// ---------------------------------------------------------------------------
__device__ __forceinline__ ull fma2(ull a, ull b, ull c)
{
    ull d;
    asm("fma.rn.f32x2 %0, %1, %2, %3;" : "=l"(d) : "l"(a), "l"(b), "l"(c));
    return d;
}
__device__ __forceinline__ void unpack2f(ull v, float& lo, float& hi)
{
    asm("mov.b64 {%0, %1}, %2;" : "=f"(lo), "=f"(hi) : "l"(v));
}
__device__ __forceinline__ void mma_f16(float* d, const u32* a, const u32* b)
{
    asm volatile(
        "mma.sync.aligned.m16n8k16.row.col.f32.f16.f16.f32 "
        "{%0,%1,%2,%3}, {%4,%5,%6,%7}, {%8,%9}, {%0,%1,%2,%3};"
        : "+f"(d[0]), "+f"(d[1]), "+f"(d[2]), "+f"(d[3])
        : "r"(a[0]), "r"(a[1]), "r"(a[2]), "r"(a[3]), "r"(b[0]), "r"(b[1]));
}
__device__ __forceinline__ u32 pack_h2(float lo, float hi)
{
    __half2 t = __floats2half2_rn(lo, hi);   // .x = lo (low 16 bits)
    return *reinterpret_cast<u32*>(&t);
}

// ---------------------------------------------------------------------------
// Prep: N recurrence, finish depth, stable rank
// ---------------------------------------------------------------------------
__global__ void prep_meta_kernel(const int* __restrict__ N)
{
    __shared__ int fin[BATCH];
    int b = threadIdx.x;
    if (b < BATCH) {
        int n = N[b];
        g_Nseq[b][0] = n;
        int f = DEPTHS - 1;
        bool done = false;
        #pragma unroll
        for (int d = 0; d < DEPTHS; ++d) {
            int m = n - KS; if (m < 0) m = 0;
            n = (m + 1) / 2 + 1;
            g_Nseq[b][d + 1] = n;
            if (!done && n <= 1) { f = d; done = true; }
        }
        fin[b] = f;
        g_finish[b] = f;
    }
    __syncthreads();
    if (b < BATCH) {
        int f = fin[b];
        int r = 0;
        #pragma unroll
        for (int j = 0; j < BATCH; ++j)
            if (fin[j] < f || (fin[j] == f && j < b)) r++;
        g_rank[b] = r;
    }
}

// ---------------------------------------------------------------------------
// Prep: tail weights (g_W4)
// ---------------------------------------------------------------------------
__global__ void prep_wt_kernel(const float* __restrict__ W)
{
    int i = blockIdx.x * blockDim.x + threadIdx.x;
    if (i < CIN * 3 * NH) {
        int o    = i & 127;
        int gate = (i >> 7) % 3;
        int c    = i / (3 * NH);
        int j    = gate * NH + o;
        const float4* src = reinterpret_cast<const float4*>(W);
        g_W4[i] = src[j * CIN + c];
    }
}

// ---------------------------------------------------------------------------
// Prep: a-fragment-ordered fp16 weights + depth-channel weights.
// g_Wfrag[((k16*NMT + mtile)*32 + lane)*4 + r] (u32 = 2 fp16)
// a-frag m16k16: reg r holds (m = mtile*16 + lane/4 + 8*(r&1),
//                             k = k16*16 + (lane%4)*2 + 8*(r>>1) + i)
// ---------------------------------------------------------------------------
__global__ void prep_wfrag_kernel(const float* __restrict__ W)
{
    int idx = blockIdx.x * blockDim.x + threadIdx.x;
    const int TOT = NK16 * NMT * 32 * 4;
    if (idx < TOT) {
        int r     = idx & 3;
        int lane  = (idx >> 2) & 31;
        int mtile = (idx >> 7) % NMT;
        int k16   = (idx >> 7) / NMT;
        u32 out = 0;
        #pragma unroll
        for (int i = 0; i < 2; ++i) {
            int m = mtile * 16 + (lane >> 2) + 8 * (r & 1);
            int k = k16 * 16 + (lane & 3) * 2 + 8 * (r >> 1) + i;
            int c = k >> 2, kap = k & 3;
            float w = W[m * (CIN * KS) + c * KS + kap];
            __half wh = __float2half_rn(w);
            out |= ((u32)*reinterpret_cast<unsigned short*>(&wh)) << (16 * i);
        }
        g_Wfrag[idx] = out;
    }
    if (idx < 384 * 4) {
        int m = idx >> 2, k = idx & 3;
        g_Wd[idx] = W[m * (CIN * KS) + 128 * KS + k];
    }
}

// ---------------------------------------------------------------------------
// HMMA depth step (d = 0..5): one block = 64 t's of one batch, full M=384.
// fp16 2-product: acc = Wh * (xh + xl), fp32 accumulate.
// ---------------------------------------------------------------------------
__global__ __launch_bounds__(MMA_NTH, 1)
void conv_mma_kernel(const float* __restrict__ hin,
                     int insel, int outsel, int in_stride,
                     int Lc, int Lout, int depth, float logd,
                     const float* __restrict__ bias)
{
    const int b  = blockIdx.y;
    const int t0 = blockIdx.x * NT;
    if (t0 >= g_Nseq[b][depth + 1]) return;

    const float* in = (insel == 0) ? hin : (insel == 1 ? g_bufA : g_bufB);
    float* out = (outsel == 1) ? g_bufA : g_bufB;

    extern __shared__ __align__(16) char smem[];
    u32* Bh = reinterpret_cast<u32*>(smem);
    u32* Bl = Bh + BH_WORDS;

    const int tid = threadIdx.x;
    const int V = min(Lc, g_Nseq[b][depth]);
    const float* xb = in + (size_t)b * NH * in_stride;

    // ---- build B (x) fragments, fp16 hi/lo ----
    for (int s = tid; s < NK16 * 8 * 32 * 2; s += MMA_NTH) {
        int reg   = s & 1;
        int lane2 = (s >> 1) & 31;
        int ntile = (s >> 6) & 7;
        int k16   = s >> 9;
        int n  = ntile * 8 + (lane2 >> 2);
        int kb = k16 * 16 + reg * 8 + (lane2 & 3) * 2;
        float v0 = 0.f, v1 = 0.f;
        {
            int c = kb >> 2, kap = kb & 3;
            int pos = 2 * (t0 + n) + kap;
            if (pos < V) v0 = xb[(size_t)c * in_stride + pos];
        }
        {
            int k = kb + 1, c = k >> 2, kap = k & 3;
            int pos = 2 * (t0 + n) + kap;
            if (pos < V) v1 = xb[(size_t)c * in_stride + pos];
        }
        __half h0 = __float2half_rn(v0);
        __half h1 = __float2half_rn(v1);
        u32 H = ((u32)*reinterpret_cast<unsigned short*>(&h0))
              | (((u32)*reinterpret_cast<unsigned short*>(&h1)) << 16);
        Bh[s] = H;
        Bl[s] = pack_h2(v0 - __half2float(h0), v1 - __half2float(h1));
    }
    __syncthreads();

    const int wid  = tid >> 5;
    const int lane = tid & 31;
    const int mw   = wid >> 1;     // 0..7
    const int nw   = wid & 1;      // 0..1

    float acc[3][4][4];
    #pragma unroll
    for (int g = 0; g < 3; ++g)
        #pragma unroll
        for (int ni = 0; ni < 4; ++ni)
            #pragma unroll
            for (int r = 0; r < 4; ++r) acc[g][ni][r] = 0.f;

    // ---- mainloop over 32 k16 fragments ----
    #pragma unroll 2
    for (int k16 = 0; k16 < NK16; ++k16) {
        u32 ah[3][4];
        #pragma unroll
        for (int g = 0; g < 3; ++g) {
            int mtile = g * 8 + mw;
            uint4 vh = *reinterpret_cast<const uint4*>(
                g_Wfrag + ((k16 * NMT + mtile) * 32 + lane) * 4);
            ah[g][0] = vh.x; ah[g][1] = vh.y; ah[g][2] = vh.z; ah[g][3] = vh.w;
        }
        u32 bh[4][2], bl[4][2];
        #pragma unroll
        for (int ni = 0; ni < 4; ++ni) {
            int ntile = nw * 4 + ni;
            uint2 vb = *reinterpret_cast<const uint2*>(
                Bh + ((k16 * 8 + ntile) * 32 + lane) * 2);
            uint2 wb = *reinterpret_cast<const uint2*>(
                Bl + ((k16 * 8 + ntile) * 32 + lane) * 2);
            bh[ni][0] = vb.x; bh[ni][1] = vb.y;
            bl[ni][0] = wb.x; bl[ni][1] = wb.y;
        }
        #pragma unroll
        for (int g = 0; g < 3; ++g)
            #pragma unroll
            for (int ni = 0; ni < 4; ++ni) {
                mma_f16(acc[g][ni], ah[g], bh[ni]);
                mma_f16(acc[g][ni], ah[g], bl[ni]);
            }
    }

    // ---- epilogue: bias + depth channel + gating ----
    const int rowa = 16 * mw + (lane >> 2);
    const int rowb = rowa + 8;
    const float biasv[2][3] = {
        { bias[rowa], bias[NH + rowa], bias[2 * NH + rowa] },
        { bias[rowb], bias[NH + rowb], bias[2 * NH + rowb] } };
    float4 wd[2][3];
    float fsum[2][3];
    #pragma unroll
    for (int rs = 0; rs < 2; ++rs)
        #pragma unroll
        for (int g = 0; g < 3; ++g) {
            int row = rs ? rowb : rowa;
            wd[rs][g] = *reinterpret_cast<const float4*>(g_Wd + (g * 128 + row) * 4);
            fsum[rs][g] = logd * (wd[rs][g].x + wd[rs][g].y + wd[rs][g].z + wd[rs][g].w);
        }

    const int fin_here = (g_finish[b] == depth);
    #pragma unroll
    for (int ni = 0; ni < 4; ++ni) {
        int col0 = t0 + 32 * nw + ni * 8 + (lane & 3) * 2;
        #pragma unroll
        for (int rs = 0; rs < 2; ++rs) {
            int row = rs ? rowb : rowa;
            float* orow = out + ((size_t)b * NH + row) * LMAX;
            #pragma unroll
            for (int cc = 0; cc < 2; ++cc) {
                int col = col0 + cc;
                if (col < Lout) {
                    int ci = rs * 2 + cc;
                    float dt[3];
                    int p2 = 2 * col;
                    if (p2 + 3 < V) {
                        dt[0] = fsum[rs][0]; dt[1] = fsum[rs][1]; dt[2] = fsum[rs][2];
                    } else {
                        float m0 = (p2 < V) ? logd : 0.f, m1 = (p2+1 < V) ? logd : 0.f;
                        float m2 = (p2+2 < V) ? logd : 0.f, m3 = (p2+3 < V) ? logd : 0.f;
                        #pragma unroll
                        for (int g = 0; g < 3; ++g)
                            dt[g] = wd[rs][g].x*m0 + wd[rs][g].y*m1
                                  + wd[rs][g].z*m2 + wd[rs][g].w*m3;
                    }
                    float l  = acc[0][ni][ci] + biasv[rs][0] + dt[0];
                    float rr = acc[1][ni][ci] + biasv[rs][1] + dt[1];
                    float ga = acc[2][ni][ci] + biasv[rs][2] + dt[2];
                    float gv = 1.0f / (1.0f + __expf(-ga));
                    float rv = tanhf(rr);
                    float hn = l * gv + rv * (1.0f - gv);
                    orow[col] = hn;
                    if (col == 0 && fin_here) g_capture[b * NH + row] = hn;
                }
            }
        }
    }
}

// ---------------------------------------------------------------------------
// Scalar tail step (d = 6..12): R2-proven kernel (fp32 exact)
// ---------------------------------------------------------------------------
__global__ __launch_bounds__(256)
void conv_tail_kernel(int insel, int outsel,
                      int Lc, int Lout, int depth, float logd,
                      const float* __restrict__ bias)
{
    const int b  = blockIdx.y;
    const int t0 = blockIdx.x * TT_OUT;

    const int Nn = g_Nseq[b][depth + 1];
    if (t0 >= Nn) return;

    const float* in = (insel == 1) ? g_bufA : g_bufB;
    float* out = (outsel == 1) ? g_bufA : g_bufB;

    __shared__ float tile[CIN][TTIN];

    const int V = min(Lc, g_Nseq[b][depth]);
    const float* inb = in + (size_t)b * NH * LMAX;

    for (int i = threadIdx.x; i < CIN * TTIN; i += 256) {
        int c = i / TTIN;
        int x = i - c * TTIN;
        int pos = 2 * t0 + x;
        float v = 0.0f;
        if (pos < V) v = (c < NH) ? inb[(size_t)c * LMAX + pos] : logd;
        tile[c][x] = v;
    }
    __syncthreads();

    const int o    = threadIdx.x & 127;
    const int half = threadIdx.x >> 7;
    const int tl0  = half * TTPT;

    ull accl[TTPT], accr[TTPT], accg[TTPT];
    #pragma unroll
    for (int tt = 0; tt < TTPT; ++tt) { accl[tt] = 0ull; accr[tt] = 0ull; accg[tt] = 0ull; }

    const ulonglong2* wbase = reinterpret_cast<const ulonglong2*>(g_W4);

    #pragma unroll 1
    for (int c = 0; c < CIN; ++c) {
        const ulonglong2 wl = wbase[(c * 3 + 0) * NH + o];
        const ulonglong2 wr = wbase[(c * 3 + 1) * NH + o];
        const ulonglong2 wg = wbase[(c * 3 + 2) * NH + o];
        const ull* xr = reinterpret_cast<const ull*>(&tile[c][2 * tl0]);
        ull x0 = xr[0];
        #pragma unroll
        for (int tt = 0; tt < TTPT; ++tt) {
            ull x1 = xr[tt + 1];
            accl[tt] = fma2(wl.x, x0, accl[tt]);
            accl[tt] = fma2(wl.y, x1, accl[tt]);
            accr[tt] = fma2(wr.x, x0, accr[tt]);
            accr[tt] = fma2(wr.y, x1, accr[tt]);
            accg[tt] = fma2(wg.x, x0, accg[tt]);
            accg[tt] = fma2(wg.y, x1, accg[tt]);
            x0 = x1;
        }
    }

    const float bl = bias[o], br = bias[NH + o], bg = bias[2 * NH + o];
    const int fin_here = (g_finish[b] == depth);
    float* outb = out + ((size_t)b * NH + o) * LMAX;

    #pragma unroll
    for (int tt = 0; tt < TTPT; ++tt) {
        int t = t0 + tl0 + tt;
        if (t < Lout) {
            float lo, hi;
            unpack2f(accl[tt], lo, hi); float l  = lo + hi + bl;
            unpack2f(accr[tt], lo, hi); float rr = lo + hi + br;
            unpack2f(accg[tt], lo, hi); float ga = lo + hi + bg;
            float gv = 1.0f / (1.0f + __expf(-ga));
            float rv = tanhf(rr);
            float hn = l * gv + rv * (1.0f - gv);
            outb[t] = hn;
            if (t == 0 && fin_here) g_capture[b * NH + o] = hn;
        }
    }
}

// ---------------------------------------------------------------------------
// Final: out[rank[b]] = capture[b]
// ---------------------------------------------------------------------------
__global__ void finalize_kernel(float* __restrict__ out)
{
    int b = blockIdx.x;
    int o = threadIdx.x;
    out[g_rank[b] * NH + o] = g_capture[b * NH + o];
}

// ---------------------------------------------------------------------------
// Launch
// ---------------------------------------------------------------------------
extern "C" void kernel_launch(void* const* d_in, const int* in_sizes, int n_in,
                              void* d_out, int out_size)
{
    const float* h    = (const float*)d_in[0];
    const int*   N    = (const int*)  d_in[1];
    const float* W    = (const float*)d_in[2];
    const float* bias = (const float*)d_in[3];
    float* out = (float*)d_out;

    const int SMEM_DYN = 2 * BH_WORDS * (int)sizeof(u32);   // 131072 B
    cudaFuncSetAttribute(conv_mma_kernel,
                         cudaFuncAttributeMaxDynamicSharedMemorySize, SMEM_DYN);

    prep_meta_kernel<<<1, 32>>>(N);
    prep_wt_kernel<<<(CIN * 3 * NH + 255) / 256, 256>>>(W);
    prep_wfrag_kernel<<<(NK16 * NMT * 32 * 4 + 255) / 256, 256>>>(W);

    static const int Lin[DEPTHS]   = {16384, 8191, 4095, 2047, 1023, 511, 255,
                                      127, 63, 31, 15, 7, 3};
    static const int LoutA[DEPTHS] = {8191, 4095, 2047, 1023, 511, 255, 127,
                                      63, 31, 15, 7, 3, 1};

    for (int d = 0; d < DEPTHS; ++d) {
        int insel  = (d == 0) ? 0 : ((d & 1) ? 1 : 2);
        int outsel = (d & 1) ? 2 : 1;
        int in_stride = (d == 0) ? L0 : LMAX;
        float logd = log1pf((float)d);
        if (d <= 5) {
            dim3 grid((LoutA[d] + NT - 1) / NT, BATCH);
            conv_mma_kernel<<<grid, MMA_NTH, SMEM_DYN>>>(
                h, insel, outsel, in_stride, Lin[d], LoutA[d], d, logd, bias);
        } else {
            dim3 grid((LoutA[d] + TT_OUT - 1) / TT_OUT, BATCH);
            conv_tail_kernel<<<grid, 256>>>(insel, outsel,
                                            Lin[d], LoutA[d], d, logd, bias);
        }
    }

    finalize_kernel<<<BATCH, NH>>>(out);
}

// round 15
// speedup vs baseline: 2.4933x; 1.1349x over previous
#include <cuda_runtime.h>
#include <cuda_fp16.h>
#include <math.h>

// ---------------------------------------------------------------------------
// Problem constants
// ---------------------------------------------------------------------------
#define BATCH 16
#define NH    128
#define L0    16384
#define KS    4
#define DEPTHS 13
#define LMAX  8192
#define CIN   129

// ---- HMMA kernel config (depths 0..5) ----
#define NT      64          // t's per block (8 n-tiles of 8)
#define NK16    32          // k16 fragments (K = 512)
#define NMT     24          // m-tiles (384 rows / 16)
#define MMA_NTH 512         // 16 warps
#define BH_WORDS (NK16 * 8 * 32 * 2)     // 16384 u32 (single fp16 B)

// ---- scalar tail config (depths 6..12) ----
#define TT_OUT 16
#define TTPT   8
#define TTIN   (2*TT_OUT + 2)

typedef unsigned long long ull;
typedef unsigned int u32;

// ---------------------------------------------------------------------------
// Device scratch
// ---------------------------------------------------------------------------
__device__ float  g_bufA[(size_t)BATCH * NH * LMAX];
__device__ float  g_bufB[(size_t)BATCH * NH * LMAX];
__device__ float4 g_W4[CIN * 3 * NH];               // tail weights (fp32)
__device__ u32    g_Wfrag[NK16 * NMT * 32 * 4];     // a-frag-ordered fp16 W
__device__ float  g_Wd[384 * 4];                    // depth-channel weights
__device__ float  g_capture[BATCH * NH];
__device__ int    g_Nseq[BATCH][DEPTHS + 1];
__device__ int    g_finish[BATCH];
__device__ int    g_rank[BATCH];

// ---------------------------------------------------------------------------
// helpers
// ---------------------------------------------------------------------------
__device__ __forceinline__ ull fma2(ull a, ull b, ull c)
{
    ull d;
    asm("fma.rn.f32x2 %0, %1, %2, %3;" : "=l"(d) : "l"(a), "l"(b), "l"(c));
    return d;
}
__device__ __forceinline__ void unpack2f(ull v, float& lo, float& hi)
{
    asm("mov.b64 {%0, %1}, %2;" : "=f"(lo), "=f"(hi) : "l"(v));
}
__device__ __forceinline__ void mma_f16(float* d, const u32* a, const u32* b)
{
    asm volatile(
        "mma.sync.aligned.m16n8k16.row.col.f32.f16.f16.f32 "
        "{%0,%1,%2,%3}, {%4,%5,%6,%7}, {%8,%9}, {%0,%1,%2,%3};"
        : "+f"(d[0]), "+f"(d[1]), "+f"(d[2]), "+f"(d[3])
        : "r"(a[0]), "r"(a[1]), "r"(a[2]), "r"(a[3]), "r"(b[0]), "r"(b[1]));
}

// ---------------------------------------------------------------------------
// Prep: N recurrence, finish depth, stable rank
// ---------------------------------------------------------------------------
__global__ void prep_meta_kernel(const int* __restrict__ N)
{
    __shared__ int fin[BATCH];
    int b = threadIdx.x;
    if (b < BATCH) {
        int n = N[b];
        g_Nseq[b][0] = n;
        int f = DEPTHS - 1;
        bool done = false;
        #pragma unroll
        for (int d = 0; d < DEPTHS; ++d) {
            int m = n - KS; if (m < 0) m = 0;
            n = (m + 1) / 2 + 1;
            g_Nseq[b][d + 1] = n;
            if (!done && n <= 1) { f = d; done = true; }
        }
        fin[b] = f;
        g_finish[b] = f;
    }
    __syncthreads();
    if (b < BATCH) {
        int f = fin[b];
        int r = 0;
        #pragma unroll
        for (int j = 0; j < BATCH; ++j)
            if (fin[j] < f || (fin[j] == f && j < b)) r++;
        g_rank[b] = r;
    }
}

// ---------------------------------------------------------------------------
// Prep: tail weights (g_W4)
// ---------------------------------------------------------------------------
__global__ void prep_wt_kernel(const float* __restrict__ W)
{
    int i = blockIdx.x * blockDim.x + threadIdx.x;
    if (i < CIN * 3 * NH) {
        int o    = i & 127;
        int gate = (i >> 7) % 3;
        int c    = i / (3 * NH);
        int j    = gate * NH + o;
        const float4* src = reinterpret_cast<const float4*>(W);
        g_W4[i] = src[j * CIN + c];
    }
}

// ---------------------------------------------------------------------------
// Prep: a-fragment-ordered fp16 weights + depth-channel weights.
// ---------------------------------------------------------------------------
__global__ void prep_wfrag_kernel(const float* __restrict__ W)
{
    int idx = blockIdx.x * blockDim.x + threadIdx.x;
    const int TOT = NK16 * NMT * 32 * 4;
    if (idx < TOT) {
        int r     = idx & 3;
        int lane  = (idx >> 2) & 31;
        int mtile = (idx >> 7) % NMT;
        int k16   = (idx >> 7) / NMT;
        u32 out = 0;
        #pragma unroll
        for (int i = 0; i < 2; ++i) {
            int m = mtile * 16 + (lane >> 2) + 8 * (r & 1);
            int k = k16 * 16 + (lane & 3) * 2 + 8 * (r >> 1) + i;
            int c = k >> 2, kap = k & 3;
            float w = W[m * (CIN * KS) + c * KS + kap];
            __half wh = __float2half_rn(w);
            out |= ((u32)*reinterpret_cast<unsigned short*>(&wh)) << (16 * i);
        }
        g_Wfrag[idx] = out;
    }
    if (idx < 384 * 4) {
        int m = idx >> 2, k = idx & 3;
        g_Wd[idx] = W[m * (CIN * KS) + 128 * KS + k];
    }
}

// ---------------------------------------------------------------------------
// HMMA depth step (d = 0..5): one block = 64 t's of one batch, full M=384.
// Single-product fp16: acc = Wh * xh, fp32 accumulate.
// ---------------------------------------------------------------------------
__global__ __launch_bounds__(MMA_NTH, 1)
void conv_mma_kernel(const float* __restrict__ hin,
                     int insel, int outsel, int in_stride,
                     int Lc, int Lout, int depth, float logd,
                     const float* __restrict__ bias)
{
    const int b  = blockIdx.y;
    const int t0 = blockIdx.x * NT;
    if (t0 >= g_Nseq[b][depth + 1]) return;

    const float* in = (insel == 0) ? hin : (insel == 1 ? g_bufA : g_bufB);
    float* out = (outsel == 1) ? g_bufA : g_bufB;

    extern __shared__ __align__(16) char smem[];
    u32* Bh = reinterpret_cast<u32*>(smem);

    const int tid = threadIdx.x;
    const int V = min(Lc, g_Nseq[b][depth]);
    const float* xb = in + (size_t)b * NH * in_stride;

    // ---- build B (x) fragments, single fp16 ----
    for (int s = tid; s < BH_WORDS; s += MMA_NTH) {
        int reg   = s & 1;
        int lane2 = (s >> 1) & 31;
        int ntile = (s >> 6) & 7;
        int k16   = s >> 9;
        int n  = ntile * 8 + (lane2 >> 2);
        int kb = k16 * 16 + reg * 8 + (lane2 & 3) * 2;
        float v0 = 0.f, v1 = 0.f;
        {
            int c = kb >> 2, kap = kb & 3;
            int pos = 2 * (t0 + n) + kap;
            if (pos < V) v0 = xb[(size_t)c * in_stride + pos];
        }
        {
            int k = kb + 1, c = k >> 2, kap = k & 3;
            int pos = 2 * (t0 + n) + kap;
            if (pos < V) v1 = xb[(size_t)c * in_stride + pos];
        }
        __half2 hv = __floats2half2_rn(v0, v1);   // .x = v0 (low 16 bits)
        Bh[s] = *reinterpret_cast<u32*>(&hv);
    }
    __syncthreads();

    const int wid  = tid >> 5;
    const int lane = tid & 31;
    const int mw   = wid >> 1;     // 0..7
    const int nw   = wid & 1;      // 0..1

    float acc[3][4][4];
    #pragma unroll
    for (int g = 0; g < 3; ++g)
        #pragma unroll
        for (int ni = 0; ni < 4; ++ni)
            #pragma unroll
            for (int r = 0; r < 4; ++r) acc[g][ni][r] = 0.f;

    // ---- mainloop over 32 k16 fragments ----
    #pragma unroll 2
    for (int k16 = 0; k16 < NK16; ++k16) {
        u32 ah[3][4];
        #pragma unroll
        for (int g = 0; g < 3; ++g) {
            int mtile = g * 8 + mw;
            uint4 vh = *reinterpret_cast<const uint4*>(
                g_Wfrag + ((k16 * NMT + mtile) * 32 + lane) * 4);
            ah[g][0] = vh.x; ah[g][1] = vh.y; ah[g][2] = vh.z; ah[g][3] = vh.w;
        }
        u32 bh[4][2];
        #pragma unroll
        for (int ni = 0; ni < 4; ++ni) {
            int ntile = nw * 4 + ni;
            uint2 vb = *reinterpret_cast<const uint2*>(
                Bh + ((k16 * 8 + ntile) * 32 + lane) * 2);
            bh[ni][0] = vb.x; bh[ni][1] = vb.y;
        }
        #pragma unroll
        for (int g = 0; g < 3; ++g)
            #pragma unroll
            for (int ni = 0; ni < 4; ++ni)
                mma_f16(acc[g][ni], ah[g], bh[ni]);
    }

    // ---- epilogue: bias + depth channel + gating ----
    const int rowa = 16 * mw + (lane >> 2);
    const int rowb = rowa + 8;
    const float biasv[2][3] = {
        { bias[rowa], bias[NH + rowa], bias[2 * NH + rowa] },
        { bias[rowb], bias[NH + rowb], bias[2 * NH + rowb] } };
    float4 wd[2][3];
    float fsum[2][3];
    #pragma unroll
    for (int rs = 0; rs < 2; ++rs)
        #pragma unroll
        for (int g = 0; g < 3; ++g) {
            int row = rs ? rowb : rowa;
            wd[rs][g] = *reinterpret_cast<const float4*>(g_Wd + (g * 128 + row) * 4);
            fsum[rs][g] = logd * (wd[rs][g].x + wd[rs][g].y + wd[rs][g].z + wd[rs][g].w);
        }

    const int fin_here = (g_finish[b] == depth);
    #pragma unroll
    for (int ni = 0; ni < 4; ++ni) {
        int col0 = t0 + 32 * nw + ni * 8 + (lane & 3) * 2;
        #pragma unroll
        for (int rs = 0; rs < 2; ++rs) {
            int row = rs ? rowb : rowa;
            float* orow = out + ((size_t)b * NH + row) * LMAX;
            #pragma unroll
            for (int cc = 0; cc < 2; ++cc) {
                int col = col0 + cc;
                if (col < Lout) {
                    int ci = rs * 2 + cc;
                    float dt[3];
                    int p2 = 2 * col;
                    if (p2 + 3 < V) {
                        dt[0] = fsum[rs][0]; dt[1] = fsum[rs][1]; dt[2] = fsum[rs][2];
                    } else {
                        float m0 = (p2 < V) ? logd : 0.f, m1 = (p2+1 < V) ? logd : 0.f;
                        float m2 = (p2+2 < V) ? logd : 0.f, m3 = (p2+3 < V) ? logd : 0.f;
                        #pragma unroll
                        for (int g = 0; g < 3; ++g)
                            dt[g] = wd[rs][g].x*m0 + wd[rs][g].y*m1
                                  + wd[rs][g].z*m2 + wd[rs][g].w*m3;
                    }
                    float l  = acc[0][ni][ci] + biasv[rs][0] + dt[0];
                    float rr = acc[1][ni][ci] + biasv[rs][1] + dt[1];
                    float ga = acc[2][ni][ci] + biasv[rs][2] + dt[2];
                    float gv = 1.0f / (1.0f + __expf(-ga));
                    float rv = tanhf(rr);
                    float hn = l * gv + rv * (1.0f - gv);
                    orow[col] = hn;
                    if (col == 0 && fin_here) g_capture[b * NH + row] = hn;
                }
            }
        }
    }
}

// ---------------------------------------------------------------------------
// Scalar tail step (d = 6..12): R2-proven kernel (fp32 exact)
// ---------------------------------------------------------------------------
__global__ __launch_bounds__(256)
void conv_tail_kernel(int insel, int outsel,
                      int Lc, int Lout, int depth, float logd,
                      const float* __restrict__ bias)
{
    const int b  = blockIdx.y;
    const int t0 = blockIdx.x * TT_OUT;

    const int Nn = g_Nseq[b][depth + 1];
    if (t0 >= Nn) return;

    const float* in = (insel == 1) ? g_bufA : g_bufB;
    float* out = (outsel == 1) ? g_bufA : g_bufB;

    __shared__ float tile[CIN][TTIN];

    const int V = min(Lc, g_Nseq[b][depth]);
    const float* inb = in + (size_t)b * NH * LMAX;

    for (int i = threadIdx.x; i < CIN * TTIN; i += 256) {
        int c = i / TTIN;
        int x = i - c * TTIN;
        int pos = 2 * t0 + x;
        float v = 0.0f;
        if (pos < V) v = (c < NH) ? inb[(size_t)c * LMAX + pos] : logd;
        tile[c][x] = v;
    }
    __syncthreads();

    const int o    = threadIdx.x & 127;
    const int half = threadIdx.x >> 7;
    const int tl0  = half * TTPT;

    ull accl[TTPT], accr[TTPT], accg[TTPT];
    #pragma unroll
    for (int tt = 0; tt < TTPT; ++tt) { accl[tt] = 0ull; accr[tt] = 0ull; accg[tt] = 0ull; }

    const ulonglong2* wbase = reinterpret_cast<const ulonglong2*>(g_W4);

    #pragma unroll 1
    for (int c = 0; c < CIN; ++c) {
        const ulonglong2 wl = wbase[(c * 3 + 0) * NH + o];
        const ulonglong2 wr = wbase[(c * 3 + 1) * NH + o];
        const ulonglong2 wg = wbase[(c * 3 + 2) * NH + o];
        const ull* xr = reinterpret_cast<const ull*>(&tile[c][2 * tl0]);
        ull x0 = xr[0];
        #pragma unroll
        for (int tt = 0; tt < TTPT; ++tt) {
            ull x1 = xr[tt + 1];
            accl[tt] = fma2(wl.x, x0, accl[tt]);
            accl[tt] = fma2(wl.y, x1, accl[tt]);
            accr[tt] = fma2(wr.x, x0, accr[tt]);
            accr[tt] = fma2(wr.y, x1, accr[tt]);
            accg[tt] = fma2(wg.x, x0, accg[tt]);
            accg[tt] = fma2(wg.y, x1, accg[tt]);
            x0 = x1;
        }
    }

    const float bl = bias[o], br = bias[NH + o], bg = bias[2 * NH + o];
    const int fin_here = (g_finish[b] == depth);
    float* outb = out + ((size_t)b * NH + o) * LMAX;

    #pragma unroll
    for (int tt = 0; tt < TTPT; ++tt) {
        int t = t0 + tl0 + tt;
        if (t < Lout) {
            float lo, hi;
            unpack2f(accl[tt], lo, hi); float l  = lo + hi + bl;
            unpack2f(accr[tt], lo, hi); float rr = lo + hi + br;
            unpack2f(accg[tt], lo, hi); float ga = lo + hi + bg;
            float gv = 1.0f / (1.0f + __expf(-ga));
            float rv = tanhf(rr);
            float hn = l * gv + rv * (1.0f - gv);
            outb[t] = hn;
            if (t == 0 && fin_here) g_capture[b * NH + o] = hn;
        }
    }
}

// ---------------------------------------------------------------------------
// Final: out[rank[b]] = capture[b]
// ---------------------------------------------------------------------------
__global__ void finalize_kernel(float* __restrict__ out)
{
    int b = blockIdx.x;
    int o = threadIdx.x;
    out[g_rank[b] * NH + o] = g_capture[b * NH + o];
}

// ---------------------------------------------------------------------------
// Launch
// ---------------------------------------------------------------------------
extern "C" void kernel_launch(void* const* d_in, const int* in_sizes, int n_in,
                              void* d_out, int out_size)
{
    const float* h    = (const float*)d_in[0];
    const int*   N    = (const int*)  d_in[1];
    const float* W    = (const float*)d_in[2];
    const float* bias = (const float*)d_in[3];
    float* out = (float*)d_out;

    const int SMEM_DYN = BH_WORDS * (int)sizeof(u32);   // 65536 B
    cudaFuncSetAttribute(conv_mma_kernel,
                         cudaFuncAttributeMaxDynamicSharedMemorySize, SMEM_DYN);

    prep_meta_kernel<<<1, 32>>>(N);
    prep_wt_kernel<<<(CIN * 3 * NH + 255) / 256, 256>>>(W);
    prep_wfrag_kernel<<<(NK16 * NMT * 32 * 4 + 255) / 256, 256>>>(W);

    static const int Lin[DEPTHS]   = {16384, 8191, 4095, 2047, 1023, 511, 255,
                                      127, 63, 31, 15, 7, 3};
    static const int LoutA[DEPTHS] = {8191, 4095, 2047, 1023, 511, 255, 127,
                                      63, 31, 15, 7, 3, 1};

    for (int d = 0; d < DEPTHS; ++d) {
        int insel  = (d == 0) ? 0 : ((d & 1) ? 1 : 2);
        int outsel = (d & 1) ? 2 : 1;
        int in_stride = (d == 0) ? L0 : LMAX;
        float logd = log1pf((float)d);
        if (d <= 5) {
            dim3 grid((LoutA[d] + NT - 1) / NT, BATCH);
            conv_mma_kernel<<<grid, MMA_NTH, SMEM_DYN>>>(
                h, insel, outsel, in_stride, Lin[d], LoutA[d], d, logd, bias);
        } else {
            dim3 grid((LoutA[d] + TT_OUT - 1) / TT_OUT, BATCH);
            conv_tail_kernel<<<grid, 256>>>(insel, outsel,
                                            Lin[d], LoutA[d], d, logd, bias);
        }
    }

    finalize_kernel<<<BATCH, NH>>>(out);
}